// round 6
// baseline (speedup 1.0000x reference)
#include <cuda_runtime.h>
#include <cuda_bf16.h>
#include <math.h>

// FusedCirculantBlock: SignFlip -> per-block rFFT(512) -> 8x8 spectral mix -> irFFT -> bias -> erf-GELU
// B=2, S=4096, F_IN=F_OUT=4096, P=512, Q_IN=Q_OUT=8.
//
// R2: persistent-CTA design. One CTA per SM, 512 threads, the full spectral
// weight table Wf (131.5 KB), bias (16 KB), sign bitmask (512 B) and twiddles
// (4 KB) resident in SMEM for the whole kernel. Each 256-thread half processes
// one token, synchronized by its own named barrier, looping over token pairs.
// Off-chip traffic reduces to streaming x and out.

#define QB 8            // blocks per side
#define NF 257          // rfft bins
#define XSTR 257        // Xf row stride inside ping buffer
#define FFTPAD 576      // 512 + 512/8 padding slots
#define TPB 512
#define HBUF (2 * 4 * FFTPAD)   // per-half workspace (ping+pong) in float2

__device__ float2   g_tw[512];          // exp(-2*pi*i*k/512)
__device__ unsigned g_sfbits[128];      // sign bits packed (bit e of word e/32)
__device__ float2   g_Wf[64 * NF];      // [o][i][f], scaled by 1/1024

static __device__ __forceinline__ int PAD(int i) { return i + (i >> 3); }

static __device__ __forceinline__ void barhalf(int id) {
    asm volatile("bar.sync %0, %1;" :: "r"(id), "r"(256) : "memory");
}

static __device__ __forceinline__ float2 cadd(float2 a, float2 b) { return make_float2(a.x + b.x, a.y + b.y); }
static __device__ __forceinline__ float2 csub(float2 a, float2 b) { return make_float2(a.x - b.x, a.y - b.y); }
static __device__ __forceinline__ float2 cmul(float2 a, float2 w) {
    return make_float2(a.x * w.x - a.y * w.y, a.x * w.y + a.y * w.x);
}
static __device__ __forceinline__ float2 cfma(float2 x, float2 w, float2 acc) {
    acc.x = fmaf(x.x, w.x, fmaf(-x.y, w.y, acc.x));
    acc.y = fmaf(x.x, w.y, fmaf(x.y, w.x, acc.y));
    return acc;
}

static __device__ __forceinline__ float gelu_erf(float v) {
    return 0.5f * v * (1.0f + erff(v * 0.70710678118654752f));
}

// 8-point DFT: b_u = sum_r a_r * w8^{u*r}; w8 = exp(-2*pi*i/8) fwd (INV=0), conj for INV=1
template <int INV>
static __device__ __forceinline__ void dft8(float2 a[8]) {
    const float C = 0.70710678118654752f;
    float2 s0 = cadd(a[0], a[4]), s1 = csub(a[0], a[4]);
    float2 s2 = cadd(a[2], a[6]), s3 = csub(a[2], a[6]);
    float2 u0 = cadd(a[1], a[5]), u1 = csub(a[1], a[5]);
    float2 u2 = cadd(a[3], a[7]), u3 = csub(a[3], a[7]);
    float2 E0 = cadd(s0, s2), E2 = csub(s0, s2);
    float2 O0 = cadd(u0, u2), O2 = csub(u0, u2);
    float2 E1, E3, O1, O3, t1, t2, t3;
    if (!INV) {
        E1 = make_float2(s1.x + s3.y, s1.y - s3.x);   // s1 - i*s3
        E3 = make_float2(s1.x - s3.y, s1.y + s3.x);   // s1 + i*s3
        O1 = make_float2(u1.x + u3.y, u1.y - u3.x);
        O3 = make_float2(u1.x - u3.y, u1.y + u3.x);
        t1 = make_float2(C * (O1.x + O1.y), C * (O1.y - O1.x));   // c(1-i)*O1
        t2 = make_float2(O2.y, -O2.x);                            // -i*O2
        t3 = make_float2(C * (O3.y - O3.x), -C * (O3.x + O3.y));  // -c(1+i)*O3
    } else {
        E1 = make_float2(s1.x - s3.y, s1.y + s3.x);   // s1 + i*s3
        E3 = make_float2(s1.x + s3.y, s1.y - s3.x);
        O1 = make_float2(u1.x - u3.y, u1.y + u3.x);
        O3 = make_float2(u1.x + u3.y, u1.y - u3.x);
        t1 = make_float2(C * (O1.x - O1.y), C * (O1.x + O1.y));   // c(1+i)*O1
        t2 = make_float2(-O2.y, O2.x);                            // +i*O2
        t3 = make_float2(-C * (O3.x + O3.y), C * (O3.x - O3.y));  // c(-1+i)*O3
    }
    a[0] = cadd(E0, O0); a[4] = csub(E0, O0);
    a[1] = cadd(E1, t1); a[5] = csub(E1, t1);
    a[2] = cadd(E2, t2); a[6] = csub(E2, t2);
    a[3] = cadd(E3, t3); a[7] = csub(E3, t3);
}

// Radix-8 Stockham FFT-512. Input in bufI; result lands in bufO.
// All 256 threads of the half must call (internal named barriers). t in [0,64).
template <int INV>
static __device__ __forceinline__ void fft512(float2* bufI, float2* bufO,
                                              const float2* tw, int t, int bid) {
    float2 a[8];
    {   // stage 0: n=512, s=1, m=64
        int p = t;
        #pragma unroll
        for (int r = 0; r < 8; r++) a[r] = bufI[PAD(p + 64 * r)];
        dft8<INV>(a);
        bufO[PAD(8 * p)] = a[0];
        #pragma unroll
        for (int u = 1; u < 8; u++) {
            float2 w = tw[(u * p) & 511];
            if (INV) w.y = -w.y;
            bufO[PAD(8 * p + u)] = cmul(a[u], w);
        }
    }
    barhalf(bid);
    {   // stage 1: n=64, s=8, m=8
        int q = t & 7, p = t >> 3;
        #pragma unroll
        for (int r = 0; r < 8; r++) a[r] = bufO[PAD(q + 8 * p + 64 * r)];
        dft8<INV>(a);
        bufI[PAD(q + 64 * p)] = a[0];
        #pragma unroll
        for (int u = 1; u < 8; u++) {
            float2 w = tw[(8 * u * p) & 511];
            if (INV) w.y = -w.y;
            bufI[PAD(q + 64 * p + 8 * u)] = cmul(a[u], w);
        }
    }
    barhalf(bid);
    {   // stage 2: n=8, s=64, m=1
        int q = t;
        #pragma unroll
        for (int r = 0; r < 8; r++) a[r] = bufI[PAD(q + 64 * r)];
        dft8<INV>(a);
        #pragma unroll
        for (int u = 0; u < 8; u++) bufO[PAD(q + 64 * u)] = a[u];
    }
    barhalf(bid);
}

// ---------------- precompute kernels (run inside the graph, cheap) ----------

__global__ void precompute_tw_sf(const int* __restrict__ sign_bits) {
    int k = threadIdx.x;  // 512 threads
    float s, c;
    sincospif((float)k / 256.0f, &s, &c);   // angle = 2*pi*k/512
    g_tw[k] = make_float2(c, -s);
    if (k < 128) {
        unsigned m = 0;
        #pragma unroll 4
        for (int b = 0; b < 32; b++)
            m |= ((unsigned)sign_bits[k * 32 + b] & 1u) << b;
        g_sfbits[k] = m;
    }
}

__global__ void precompute_wf(const float* __restrict__ w) {
    __shared__ float2 stw[512];
    __shared__ float  sw[512];
    int blk = blockIdx.x;  // o*8+i
    for (int k = threadIdx.x; k < 512; k += blockDim.x) {
        stw[k] = g_tw[k];
        sw[k] = w[blk * 512 + k];
    }
    __syncthreads();
    for (int f = threadIdx.x; f <= 256; f += blockDim.x) {
        float re = 0.0f, im = 0.0f;
        for (int n = 0; n < 512; n++) {
            float2 t = stw[(f * n) & 511];
            float wv = sw[n];
            re = fmaf(wv, t.x, re);
            im = fmaf(wv, t.y, im);
        }
        // fold 1/2 (rfft pack skips /2 -> X stored as 2X) and 1/512 (inverse scale)
        g_Wf[blk * NF + f] = make_float2(re * (1.0f / 1024.0f), im * (1.0f / 1024.0f));
    }
}

// ---------------- main fused persistent kernel ------------------------------
// grid = #SMs, 512 threads. SMEM:
//   tw[512] f2 | Wf[64*257] f2 | buf[2 halves][2][4*576] f2 | bias[4096] f | bits[128] u32

__global__ void __launch_bounds__(TPB, 1)
fused_main(const float* __restrict__ x, const float* __restrict__ bias,
           float* __restrict__ out, int npairs) {
    extern __shared__ float2 sm[];
    float2*   s_tw  = sm;                         // 512 f2
    float2*   s_Wf  = sm + 512;                   // 16448 f2
    float2*   s_buf = sm + 512 + 64 * NF;         // 2*HBUF = 9216 f2
    float*    s_bias = (float*)(s_buf + 2 * HBUF);        // 4096 f
    unsigned* s_bits = (unsigned*)(s_bias + 4096);        // 128 u32

    const int tid  = threadIdx.x;
    const int half = tid >> 8;       // token within pair
    const int r    = tid & 255;
    const int j    = r >> 6;         // pair/fft-group id 0..3
    const int t6   = r & 63;
    const int bid  = 1 + half;       // named barrier id for this half

    // ---- one-time SMEM fill ----
    {
        const float4* Wsrc = (const float4*)g_Wf;          // 8224 float4
        float4*       Wdst = (float4*)s_Wf;
        for (int k = tid; k < 8224; k += TPB) Wdst[k] = Wsrc[k];
        for (int k = tid; k < 512; k += TPB) s_tw[k] = g_tw[k];
        const float4* bsrc = (const float4*)bias;
        float4*       bdst = (float4*)s_bias;
        for (int k = tid; k < 1024; k += TPB) bdst[k] = bsrc[k];
        if (tid < 128) s_bits[tid] = g_sfbits[tid];
    }
    __syncthreads();

    float2* bufA = s_buf + half * HBUF;       // ping (4*576)
    float2* bufB = bufA + 4 * FFTPAD;         // pong (4*576)

    for (int pr = blockIdx.x; pr < npairs; pr += gridDim.x) {
        const long long tok = (long long)pr * 2 + half;
        const float* xr   = x + tok * 4096 + j * 1024;
        float*       orow = out + tok * 4096 + j * 1024;

        // ---- pack + sign flip: (x_{2j} + i x_{2j+1}) -> bufA ----
        {
            float2* A = bufA + j * FFTPAD;
            #pragma unroll
            for (int k = 0; k < 8; k++) {
                int n = t6 + 64 * k;
                int e0 = j * 1024 + n;
                int e1 = e0 + 512;
                unsigned b0 = (s_bits[e0 >> 5] >> (e0 & 31)) & 1u;
                unsigned b1 = (s_bits[e1 >> 5] >> (e1 & 31)) & 1u;
                float re = __int_as_float(__float_as_int(xr[n])       ^ (b0 << 31));
                float im = __int_as_float(__float_as_int(xr[n + 512]) ^ (b1 << 31));
                A[PAD(n)] = make_float2(re, im);
            }
        }
        barhalf(bid);

        // ---- forward FFT: bufA -> bufB ----
        fft512<0>(bufA + j * FFTPAD, bufB + j * FFTPAD, s_tw, t6, bid);

        // ---- unpack Z -> Xf (2*X; the 1/2 is folded into Wf), into bufA ----
        {
            float2* Z  = bufB + j * FFTPAD;
            float2* X0 = bufA + (2 * j) * XSTR;
            float2* X1 = X0 + XSTR;
            for (int f = t6; f <= 256; f += 64) {
                float2 zf = Z[PAD(f)];
                float2 zm = Z[PAD((512 - f) & 511)];
                X0[f] = make_float2(zf.x + zm.x, zf.y - zm.y);   //   Z + conj(Zm)
                X1[f] = make_float2(zf.y + zm.y, zm.x - zf.x);   // -i(Z - conj(Zm))
            }
        }
        barhalf(bid);

        // ---- 8x8 spectral mix + Hermitian pack: bufA(Xf) -> bufB(Z) ----
        {
            const int opair = j;
            for (int f = t6; f <= 256; f += 64) {
                const float2* Wp0 = s_Wf + (2 * opair) * (QB * NF) + f;
                const float2* Wp1 = Wp0 + QB * NF;
                const float2* Xp  = bufA + f;
                float2 y0 = make_float2(0.f, 0.f), y1 = make_float2(0.f, 0.f);
                #pragma unroll
                for (int i = 0; i < 8; i++) {
                    float2 xv = Xp[i * XSTR];
                    y0 = cfma(xv, Wp0[i * NF], y0);
                    y1 = cfma(xv, Wp1[i * NF], y1);
                }
                float2* Zb = bufB + opair * FFTPAD;
                if (f == 0 || f == 256) {
                    Zb[PAD(f)] = make_float2(y0.x, y1.x);  // DC/Nyquist: real parts
                } else {
                    Zb[PAD(f)]       = make_float2(y0.x - y1.y, y0.y + y1.x); // Y0 + i*Y1
                    Zb[PAD(512 - f)] = make_float2(y0.x + y1.y, y1.x - y0.y); // conj ext.
                }
            }
        }
        barhalf(bid);

        // ---- inverse FFT: bufB -> bufA ----
        fft512<1>(bufB + j * FFTPAD, bufA + j * FFTPAD, s_tw, t6, bid);

        // ---- epilogue: bias + erf-GELU -> out ----
        {
            const float2* Sj = bufA + j * FFTPAD;
            const float*  br = s_bias + j * 1024;
            #pragma unroll
            for (int k = 0; k < 8; k++) {
                int n = t6 + 64 * k;
                float2 v = Sj[PAD(n)];
                orow[n]       = gelu_erf(v.x + br[n]);
                orow[n + 512] = gelu_erf(v.y + br[n + 512]);
            }
        }
        barhalf(bid);   // bufA free for next iteration's pack
    }
}

// ---------------- launch ----------------------------------------------------

extern "C" void kernel_launch(void* const* d_in, const int* in_sizes, int n_in,
                              void* d_out, int out_size) {
    const float* x         = (const float*)d_in[0];
    const float* w         = (const float*)d_in[1];
    const float* bias      = (const float*)d_in[2];
    const int*   sign_bits = (const int*)d_in[3];
    float* out = (float*)d_out;

    const int BS = in_sizes[0] / 4096;   // 8192 tokens
    const int npairs = BS / 2;

    int sms = 148;
    cudaDeviceGetAttribute(&sms, cudaDevAttrMultiProcessorCount, 0);

    // SMEM: (512 + 64*257 + 2*HBUF) float2 + 4096 float + 128 u32 = 226304 B
    const size_t smem = (size_t)(512 + 64 * NF + 2 * HBUF) * sizeof(float2)
                      + 4096 * sizeof(float) + 128 * sizeof(unsigned);

    cudaFuncSetAttribute(fused_main, cudaFuncAttributeMaxDynamicSharedMemorySize, (int)smem);

    precompute_tw_sf<<<1, 512>>>(sign_bits);
    precompute_wf<<<64, 256>>>(w);
    fused_main<<<sms, TPB, smem>>>(x, bias, out, npairs);
}

// round 10
// speedup vs baseline: 1.2934x; 1.2934x over previous
#include <cuda_runtime.h>
#include <cuda_bf16.h>
#include <math.h>

// FusedCirculantBlock: SignFlip -> per-block rFFT(512) -> 8x8 spectral mix -> irFFT -> bias -> erf-GELU
// B=2, S=4096, F_IN=F_OUT=4096, P=512, Q_IN=Q_OUT=8.
//
// R3: smem-traffic-minimized version. 256 threads/CTA, one token PAIR per CTA,
// 3 CTAs/SM. Forward stage-0 fused with global load+signflip (registers),
// inverse stage-2 fused with bias+GELU epilogue (registers->global).
// Twiddles built by register recurrence from one LDS base value.
// FFT groups (64 threads) sync via their own named barrier; only 2 CTA-wide
// syncs per pair (around the all-to-all spectral mix). Wf/bias stay in L2.

#define QB 8            // blocks per side
#define NF 257          // rfft bins
#define FFTPAD 576      // 512 + 512/8 padding slots
#define TPB 256

__device__ float2   g_tw[512];          // exp(-2*pi*i*k/512)
__device__ unsigned g_sfbits[128];      // sign bits packed
__device__ float4   g_Wfp[64 * NF];     // [opair][i][f] -> (reE,imE,reO,imO), scaled 1/1024

static __device__ __forceinline__ int PAD(int i) { return i + (i >> 3); }

static __device__ __forceinline__ void bar64(int id) {
    asm volatile("bar.sync %0, %1;" :: "r"(id), "r"(64) : "memory");
}

static __device__ __forceinline__ float2 cadd(float2 a, float2 b) { return make_float2(a.x + b.x, a.y + b.y); }
static __device__ __forceinline__ float2 csub(float2 a, float2 b) { return make_float2(a.x - b.x, a.y - b.y); }
static __device__ __forceinline__ float2 cmul(float2 a, float2 w) {
    return make_float2(a.x * w.x - a.y * w.y, a.x * w.y + a.y * w.x);
}
static __device__ __forceinline__ float2 cfma(float2 x, float2 w, float2 acc) {
    acc.x = fmaf(x.x, w.x, fmaf(-x.y, w.y, acc.x));
    acc.y = fmaf(x.x, w.y, fmaf(x.y, w.x, acc.y));
    return acc;
}

static __device__ __forceinline__ float gelu_erf(float v) {
    return 0.5f * v * (1.0f + erff(v * 0.70710678118654752f));
}

// 8-point DFT: b_u = sum_r a_r * w8^{u*r}; w8 = exp(-2*pi*i/8) fwd (INV=0), conj for INV=1
template <int INV>
static __device__ __forceinline__ void dft8(float2 a[8]) {
    const float C = 0.70710678118654752f;
    float2 s0 = cadd(a[0], a[4]), s1 = csub(a[0], a[4]);
    float2 s2 = cadd(a[2], a[6]), s3 = csub(a[2], a[6]);
    float2 u0 = cadd(a[1], a[5]), u1 = csub(a[1], a[5]);
    float2 u2 = cadd(a[3], a[7]), u3 = csub(a[3], a[7]);
    float2 E0 = cadd(s0, s2), E2 = csub(s0, s2);
    float2 O0 = cadd(u0, u2), O2 = csub(u0, u2);
    float2 E1, E3, O1, O3, t1, t2, t3;
    if (!INV) {
        E1 = make_float2(s1.x + s3.y, s1.y - s3.x);   // s1 - i*s3
        E3 = make_float2(s1.x - s3.y, s1.y + s3.x);   // s1 + i*s3
        O1 = make_float2(u1.x + u3.y, u1.y - u3.x);
        O3 = make_float2(u1.x - u3.y, u1.y + u3.x);
        t1 = make_float2(C * (O1.x + O1.y), C * (O1.y - O1.x));   // c(1-i)*O1
        t2 = make_float2(O2.y, -O2.x);                            // -i*O2
        t3 = make_float2(C * (O3.y - O3.x), -C * (O3.x + O3.y));  // -c(1+i)*O3
    } else {
        E1 = make_float2(s1.x - s3.y, s1.y + s3.x);   // s1 + i*s3
        E3 = make_float2(s1.x + s3.y, s1.y - s3.x);
        O1 = make_float2(u1.x - u3.y, u1.y + u3.x);
        O3 = make_float2(u1.x + u3.y, u1.y - u3.x);
        t1 = make_float2(C * (O1.x - O1.y), C * (O1.x + O1.y));   // c(1+i)*O1
        t2 = make_float2(-O2.y, O2.x);                            // +i*O2
        t3 = make_float2(-C * (O3.x + O3.y), C * (O3.x - O3.y));  // c(-1+i)*O3
    }
    a[0] = cadd(E0, O0); a[4] = csub(E0, O0);
    a[1] = cadd(E1, t1); a[5] = csub(E1, t1);
    a[2] = cadd(E2, t2); a[6] = csub(E2, t2);
    a[3] = cadd(E3, t3); a[7] = csub(E3, t3);
}

// Build w^2..w^7 from w with short chains (max depth 3 cmuls).
static __device__ __forceinline__ void wpow7(const float2 w1, float2 w[8]) {
    w[1] = w1;
    w[2] = cmul(w1, w1);
    w[3] = cmul(w[2], w1);
    w[4] = cmul(w[2], w[2]);
    w[5] = cmul(w[3], w[2]);
    w[6] = cmul(w[3], w[3]);
    w[7] = cmul(w[4], w[3]);
}

// ---------------- precompute kernels (run inside the graph, cheap) ----------

__global__ void precompute_tw_sf(const int* __restrict__ sign_bits) {
    int k = threadIdx.x;  // 512 threads
    float s, c;
    sincospif((float)k / 256.0f, &s, &c);   // angle = 2*pi*k/512
    g_tw[k] = make_float2(c, -s);
    if (k < 128) {
        unsigned m = 0;
        #pragma unroll 4
        for (int b = 0; b < 32; b++)
            m |= ((unsigned)sign_bits[k * 32 + b] & 1u) << b;
        g_sfbits[k] = m;
    }
}

__global__ void precompute_wf(const float* __restrict__ w) {
    __shared__ float2 stw[512];
    __shared__ float  sw[512];
    int blk = blockIdx.x;           // o*8+i
    int o = blk >> 3, i = blk & 7;
    int opair = o >> 1, slot = o & 1;
    for (int k = threadIdx.x; k < 512; k += blockDim.x) {
        stw[k] = g_tw[k];
        sw[k] = w[blk * 512 + k];
    }
    __syncthreads();
    for (int f = threadIdx.x; f <= 256; f += blockDim.x) {
        float re = 0.0f, im = 0.0f;
        for (int n = 0; n < 512; n++) {
            float2 t = stw[(f * n) & 511];
            float wv = sw[n];
            re = fmaf(wv, t.x, re);
            im = fmaf(wv, t.y, im);
        }
        // fold 1/2 (rfft pack skips /2 -> X stored as 2X) and 1/512 (inverse scale)
        float2* dst = ((float2*)g_Wfp) + ((size_t)((opair * QB + i) * NF + f) * 2 + slot);
        *dst = make_float2(re * (1.0f / 1024.0f), im * (1.0f / 1024.0f));
    }
}

// ---------------- main fused kernel ----------------------------------------
// grid = BS/2 blocks, 256 threads, 3 CTAs/SM.
// SMEM (float2): tw[512] | ping[4*576] | pong[4*576] | Xf[2*8*257] (reused as
// inverse scratch S) | bits[128 u32]

__global__ void __launch_bounds__(TPB, 3)
fused_main(const float* __restrict__ x, const float* __restrict__ bias,
           float* __restrict__ out) {
    extern __shared__ float2 sm[];
    float2*   s_tw  = sm;                     // 512
    float2*   ping  = sm + 512;               // 2304
    float2*   pong  = ping + 4 * FFTPAD;      // 2304
    float2*   s_Xf  = pong + 4 * FFTPAD;      // 4112
    unsigned* s_bits = (unsigned*)(s_Xf + 2 * QB * NF);  // 128 u32

    const int tid = threadIdx.x;
    const int j   = tid >> 6;       // fft group / output-pair id 0..3
    const int t6  = tid & 63;
    const int bid = j + 1;          // named barrier for this group

    for (int k = tid; k < 512; k += TPB) s_tw[k] = g_tw[k];
    if (tid < 128) s_bits[tid] = g_sfbits[tid];
    __syncthreads();

    const long long tok0 = (long long)blockIdx.x * 2;
    float2* Pg = ping + j * FFTPAD;
    float2* Qg = pong + j * FFTPAD;
    const int q = t6 & 7, p3 = t6 >> 3;

    // ---------------- forward FFTs (both tokens) ----------------
    #pragma unroll 1
    for (int tk = 0; tk < 2; tk++) {
        const float* xr = x + (tok0 + tk) * 4096 + j * 1024;
        float2 a[8];
        // stage 0 fused with global load + sign flip (p = t6)
        #pragma unroll
        for (int r = 0; r < 8; r++) {
            int n = t6 + 64 * r;
            int e0 = j * 1024 + n, e1 = e0 + 512;
            unsigned b0 = (s_bits[e0 >> 5] >> (e0 & 31)) & 1u;
            unsigned b1 = (s_bits[e1 >> 5] >> (e1 & 31)) & 1u;
            a[r].x = __int_as_float(__float_as_int(xr[n])       ^ (b0 << 31));
            a[r].y = __int_as_float(__float_as_int(xr[n + 512]) ^ (b1 << 31));
        }
        dft8<0>(a);
        {
            float2 w[8]; wpow7(s_tw[t6], w);
            Qg[PAD(8 * t6)] = a[0];
            #pragma unroll
            for (int u = 1; u < 8; u++) Qg[PAD(8 * t6 + u)] = cmul(a[u], w[u]);
        }
        bar64(bid);
        // stage 1 (q = t6&7, p = t6>>3)
        #pragma unroll
        for (int r = 0; r < 8; r++) a[r] = Qg[PAD(q + 8 * p3 + 64 * r)];
        dft8<0>(a);
        {
            float2 w[8]; wpow7(s_tw[8 * p3], w);
            Pg[PAD(q + 64 * p3)] = a[0];
            #pragma unroll
            for (int u = 1; u < 8; u++) Pg[PAD(q + 64 * p3 + 8 * u)] = cmul(a[u], w[u]);
        }
        bar64(bid);
        // stage 2 (no twiddles)
        #pragma unroll
        for (int r = 0; r < 8; r++) a[r] = Pg[PAD(t6 + 64 * r)];
        dft8<0>(a);
        #pragma unroll
        for (int u = 0; u < 8; u++) Qg[PAD(t6 + 64 * u)] = a[u];
        bar64(bid);
        // unpack Z -> X_{2j}, X_{2j+1} (2*X; the 1/2 is folded into Wf)
        float2* X0 = s_Xf + tk * (QB * NF) + (2 * j) * NF;
        float2* X1 = X0 + NF;
        for (int f = t6; f <= 256; f += 64) {
            float2 zf = Qg[PAD(f)];
            float2 zm = Qg[PAD((512 - f) & 511)];
            X0[f] = make_float2(zf.x + zm.x, zf.y - zm.y);   //   Z + conj(Zm)
            X1[f] = make_float2(zf.y + zm.y, zm.x - zf.x);   // -i(Z - conj(Zm))
        }
        bar64(bid);   // Qg free for next token's stage-0 writes
    }
    __syncthreads();   // all groups' Xf ready (all-to-all read next)

    // ---------------- 8x8 spectral mix + Hermitian pack ---------------------
    // group j computes output blocks (2j, 2j+1); Zb(tk=0)->ping, (tk=1)->pong
    for (int f = t6; f <= 256; f += 64) {
        const float4* Wp = g_Wfp + (size_t)(j * QB) * NF + f;
        float4 wv[8];
        #pragma unroll
        for (int i = 0; i < 8; i++) wv[i] = Wp[i * NF];
        #pragma unroll
        for (int tk = 0; tk < 2; tk++) {
            const float2* Xp = s_Xf + tk * (QB * NF) + f;
            float2 y0 = make_float2(0.f, 0.f), y1 = make_float2(0.f, 0.f);
            #pragma unroll
            for (int i = 0; i < 8; i++) {
                float2 xv = Xp[i * NF];
                y0 = cfma(xv, make_float2(wv[i].x, wv[i].y), y0);
                y1 = cfma(xv, make_float2(wv[i].z, wv[i].w), y1);
            }
            float2* Zb = (tk ? Qg : Pg);
            if (f == 0 || f == 256) {
                Zb[PAD(f)] = make_float2(y0.x, y1.x);  // DC/Nyquist: real parts
            } else {
                Zb[PAD(f)]       = make_float2(y0.x - y1.y, y0.y + y1.x); // Y0 + i*Y1
                Zb[PAD(512 - f)] = make_float2(y0.x + y1.y, y1.x - y0.y); // conj ext.
            }
        }
    }
    __syncthreads();   // all mixes done; Xf region now reusable as scratch S

    // ---------------- inverse FFTs + fused epilogue --------------------------
    float2* Sg = s_Xf + j * FFTPAD;   // 4*576 = 2304 <= 4112
    #pragma unroll 1
    for (int tk = 0; tk < 2; tk++) {
        float2* Zg = (tk ? Qg : Pg);
        float2 a[8];
        // inv stage 0 (p = t6): Zg -> Sg
        #pragma unroll
        for (int r = 0; r < 8; r++) a[r] = Zg[PAD(t6 + 64 * r)];
        dft8<1>(a);
        {
            float2 b = s_tw[t6]; b.y = -b.y;       // conj
            float2 w[8]; wpow7(b, w);
            Sg[PAD(8 * t6)] = a[0];
            #pragma unroll
            for (int u = 1; u < 8; u++) Sg[PAD(8 * t6 + u)] = cmul(a[u], w[u]);
        }
        bar64(bid);
        // inv stage 1: Sg -> Zg
        #pragma unroll
        for (int r = 0; r < 8; r++) a[r] = Sg[PAD(q + 8 * p3 + 64 * r)];
        dft8<1>(a);
        {
            float2 b = s_tw[8 * p3]; b.y = -b.y;
            float2 w[8]; wpow7(b, w);
            Zg[PAD(q + 64 * p3)] = a[0];
            #pragma unroll
            for (int u = 1; u < 8; u++) Zg[PAD(q + 64 * p3 + 8 * u)] = cmul(a[u], w[u]);
        }
        bar64(bid);
        // inv stage 2 fused with bias + erf-GELU epilogue (registers -> global)
        #pragma unroll
        for (int r = 0; r < 8; r++) a[r] = Zg[PAD(t6 + 64 * r)];
        dft8<1>(a);
        {
            const float* br   = bias + j * 1024;
            float*       orow = out + (tok0 + tk) * 4096 + j * 1024;
            #pragma unroll
            for (int u = 0; u < 8; u++) {
                int n = t6 + 64 * u;
                orow[n]       = gelu_erf(a[u].x + br[n]);
                orow[n + 512] = gelu_erf(a[u].y + br[n + 512]);
            }
        }
        // no barrier needed: tk=1 touches Sg only after its own group's
        // stage-1 barrier ordered all Sg reads of tk=0.
    }
}

// ---------------- launch ----------------------------------------------------

extern "C" void kernel_launch(void* const* d_in, const int* in_sizes, int n_in,
                              void* d_out, int out_size) {
    const float* x         = (const float*)d_in[0];
    const float* w         = (const float*)d_in[1];
    const float* bias      = (const float*)d_in[2];
    const int*   sign_bits = (const int*)d_in[3];
    float* out = (float*)d_out;

    const int BS = in_sizes[0] / 4096;   // 8192 tokens

    // SMEM: (512 + 2*4*576 + 2*8*257) float2 + 128 u32 = 74368 B -> 3 CTAs/SM
    const size_t smem = (size_t)(512 + 2 * 4 * FFTPAD + 2 * QB * NF) * sizeof(float2)
                      + 128 * sizeof(unsigned);

    cudaFuncSetAttribute(fused_main, cudaFuncAttributeMaxDynamicSharedMemorySize, (int)smem);

    precompute_tw_sf<<<1, 512>>>(sign_bits);
    precompute_wf<<<64, 256>>>(w);
    fused_main<<<BS / 2, TPB, smem>>>(x, bias, out);
}